// round 3
// baseline (speedup 1.0000x reference)
#include <cuda_runtime.h>
#include <cuda_bf16.h>
#include <math.h>

// Problem constants
#define NN      8000
#define NFEAT   512
#define NHID    128
#define NCLS    64
#define CAP     96        // max neighbors per row (E[deg]=16; huge margin)
#define EPS     1e-12f

#define AST 20            // As smem stride (16 + 4 pad)
#define BST 136           // Bs smem stride (128 + 8 pad)

#define GEMM_BLOCKS 125               // NN/64
#define EXT_BLOCKS  2000              // NN/4 (4 warps per block, 1 row per warp)
#define MEGA_BLOCKS (GEMM_BLOCKS + EXT_BLOCKS + 1)

// ---------------- scratch (device globals; no allocation allowed) ------------
__device__ float g_h     [NN * NHID];   // h = relu(x@W0+b0) == h0
__device__ float g_li0   [NN * NHID];
__device__ float g_yhat  [NN * NCLS];
__device__ int   g_cols  [NN * CAP];
__device__ float g_w     [NN * CAP];
__device__ int   g_deg   [NN];
__device__ int   g_cnt   [NN];          // multiplicity of row in idx_train

// ---------------- helpers ----------------------------------------------------
__device__ __forceinline__ unsigned f2tf(float f) {
    unsigned u;
    asm("cvt.rna.tf32.f32 %0, %1;" : "=r"(u) : "f"(f));
    return u;
}

#define MMA_TF32(cc, a, b0_, b1_)                                              \
    asm volatile(                                                              \
        "mma.sync.aligned.m16n8k8.row.col.f32.tf32.tf32.f32 "                  \
        "{%0,%1,%2,%3}, {%4,%5,%6,%7}, {%8,%9}, {%0,%1,%2,%3};"                \
        : "+f"(cc[0]), "+f"(cc[1]), "+f"(cc[2]), "+f"(cc[3])                   \
        : "r"(a[0]), "r"(a[1]), "r"(a[2]), "r"(a[3]), "r"(b0_), "r"(b1_))

// =============================================================================
// MEGA KERNEL 1: gemm1 (tensor tf32-split) + adj sparse extraction + train cnt
// =============================================================================
__global__ __launch_bounds__(128) void mega1(const float* __restrict__ x,
                                             const float* __restrict__ W0,
                                             const float* __restrict__ b0,
                                             const float* __restrict__ adj,
                                             const int*   __restrict__ idx_tr) {
    const int bid = blockIdx.x;
    const int tid = threadIdx.x;

    if (bid < GEMM_BLOCKS) {
        // ---------- GEMM1: h = relu(x @ W0 + b0), BM=64 BN=128 BK=16 ---------
        __shared__ unsigned Ah[64 * AST], Al[64 * AST];
        __shared__ unsigned Bh[16 * BST], Bl[16 * BST];

        const int warp = tid >> 5;
        const int lane = tid & 31;
        const int m0   = bid * 64;
        const int wm   = (warp & 1) * 32;
        const int wn   = (warp >> 1) * 64;

        float c[2][8][4];
#pragma unroll
        for (int mt = 0; mt < 2; mt++)
#pragma unroll
            for (int nt = 0; nt < 8; nt++)
#pragma unroll
                for (int r = 0; r < 4; r++) c[mt][nt][r] = 0.0f;

        const int ra = tid >> 1, ca = (tid & 1) * 8;
        const int rb = tid >> 3, cb = (tid & 7) * 16;
        float4 xa[2], wb[4];

        {
            const float* xp = x + (size_t)(m0 + ra) * NFEAT + ca;
            xa[0] = *(const float4*)(xp);
            xa[1] = *(const float4*)(xp + 4);
            const float* wp = W0 + (size_t)rb * NHID + cb;
#pragma unroll
            for (int i = 0; i < 4; i++) wb[i] = *(const float4*)(wp + i * 4);
        }

        for (int it = 0; it < 32; it++) {
            {
                const float* av = (const float*)xa;
#pragma unroll
                for (int j = 0; j < 8; j++) {
                    float v  = av[j];
                    unsigned hb = f2tf(v);
                    Ah[ra * AST + ca + j] = hb;
                    Al[ra * AST + ca + j] = f2tf(v - __uint_as_float(hb));
                }
                const float* bv = (const float*)wb;
#pragma unroll
                for (int j = 0; j < 16; j++) {
                    float v  = bv[j];
                    unsigned hb = f2tf(v);
                    Bh[rb * BST + cb + j] = hb;
                    Bl[rb * BST + cb + j] = f2tf(v - __uint_as_float(hb));
                }
            }
            __syncthreads();

            if (it < 31) {
                int k0 = (it + 1) * 16;
                const float* xp = x + (size_t)(m0 + ra) * NFEAT + k0 + ca;
                xa[0] = *(const float4*)(xp);
                xa[1] = *(const float4*)(xp + 4);
                const float* wp = W0 + (size_t)(k0 + rb) * NHID + cb;
#pragma unroll
                for (int i = 0; i < 4; i++) wb[i] = *(const float4*)(wp + i * 4);
            }

#pragma unroll
            for (int ks = 0; ks < 16; ks += 8) {
                unsigned ah[2][4], al[2][4];
                const int arow = wm + (lane >> 2);
                const int ac   = ks + (lane & 3);
#pragma unroll
                for (int mt = 0; mt < 2; mt++) {
                    int r = arow + mt * 16;
                    ah[mt][0] = Ah[r * AST + ac];
                    ah[mt][1] = Ah[(r + 8) * AST + ac];
                    ah[mt][2] = Ah[r * AST + ac + 4];
                    ah[mt][3] = Ah[(r + 8) * AST + ac + 4];
                    al[mt][0] = Al[r * AST + ac];
                    al[mt][1] = Al[(r + 8) * AST + ac];
                    al[mt][2] = Al[r * AST + ac + 4];
                    al[mt][3] = Al[(r + 8) * AST + ac + 4];
                }
#pragma unroll
                for (int nt = 0; nt < 8; nt++) {
                    const int bn = wn + nt * 8 + (lane >> 2);
                    const int bk = ks + (lane & 3);
                    unsigned bh0 = Bh[bk * BST + bn];
                    unsigned bh1 = Bh[(bk + 4) * BST + bn];
                    unsigned bl0 = Bl[bk * BST + bn];
                    unsigned bl1 = Bl[(bk + 4) * BST + bn];
#pragma unroll
                    for (int mt = 0; mt < 2; mt++) {
                        MMA_TF32(c[mt][nt], ah[mt], bh0, bh1);
                        MMA_TF32(c[mt][nt], ah[mt], bl0, bl1);
                        MMA_TF32(c[mt][nt], al[mt], bh0, bh1);
                    }
                }
            }
            __syncthreads();
        }

#pragma unroll
        for (int nt = 0; nt < 8; nt++) {
            int col = wn + nt * 8 + 2 * (lane & 3);
            float bias0 = b0[col], bias1 = b0[col + 1];
#pragma unroll
            for (int mt = 0; mt < 2; mt++) {
                int r = m0 + wm + mt * 16 + (lane >> 2);
                g_h[(size_t)r * NHID + col]           = fmaxf(c[mt][nt][0] + bias0, 0.0f);
                g_h[(size_t)r * NHID + col + 1]       = fmaxf(c[mt][nt][1] + bias1, 0.0f);
                g_h[(size_t)(r + 8) * NHID + col]     = fmaxf(c[mt][nt][2] + bias0, 0.0f);
                g_h[(size_t)(r + 8) * NHID + col + 1] = fmaxf(c[mt][nt][3] + bias1, 0.0f);
            }
        }
    } else if (bid < GEMM_BLOCKS + EXT_BLOCKS) {
        // ---------- adjacency extraction: 1 warp per row ---------------------
        int row_id = (bid - GEMM_BLOCKS) * 4 + (tid >> 5);
        int lane = tid & 31;
        const float* row = adj + (size_t)row_id * NN;
        int base = 0;
        // 8000 = 62*128 + 64
        for (int c0 = 0; c0 < 7936; c0 += 128) {
            float4 v = *(const float4*)(row + c0 + lane * 4);
            unsigned m4 = (v.x != 0.0f) | ((v.y != 0.0f) << 1) |
                          ((v.z != 0.0f) << 2) | ((v.w != 0.0f) << 3);
            int nz = __popc(m4);
            int sc = nz;
#pragma unroll
            for (int o = 1; o < 32; o <<= 1) {
                int t = __shfl_up_sync(0xffffffffu, sc, o);
                if (lane >= o) sc += t;
            }
            int total = __shfl_sync(0xffffffffu, sc, 31);
            if (m4) {
                int p = base + sc - nz;
                int col = c0 + lane * 4;
                if (m4 & 1) { if (p < CAP) g_cols[row_id * CAP + p] = col;     p++; }
                if (m4 & 2) { if (p < CAP) g_cols[row_id * CAP + p] = col + 1; p++; }
                if (m4 & 4) { if (p < CAP) g_cols[row_id * CAP + p] = col + 2; p++; }
                if (m4 & 8) { if (p < CAP) g_cols[row_id * CAP + p] = col + 3; }
            }
            base += total;
        }
        {
            float2 v = *(const float2*)(row + 7936 + lane * 2);
            unsigned m2 = (v.x != 0.0f) | ((v.y != 0.0f) << 1);
            int nz = __popc(m2);
            int sc = nz;
#pragma unroll
            for (int o = 1; o < 32; o <<= 1) {
                int t = __shfl_up_sync(0xffffffffu, sc, o);
                if (lane >= o) sc += t;
            }
            int total = __shfl_sync(0xffffffffu, sc, 31);
            if (m2) {
                int p = base + sc - nz;
                int col = 7936 + lane * 2;
                if (m2 & 1) { if (p < CAP) g_cols[row_id * CAP + p] = col;     p++; }
                if (m2 & 2) { if (p < CAP) g_cols[row_id * CAP + p] = col + 1; }
            }
            base += total;
        }
        if (lane == 0) g_deg[row_id] = base < CAP ? base : CAP;
    } else {
        // ---------- train-index multiplicity counts --------------------------
        for (int i = tid; i < NN; i += 128) g_cnt[i] = 0;
        __syncthreads();
        for (int i = tid; i < 500; i += 128) atomicAdd(&g_cnt[idx_tr[i]], 1);
    }
}

// =============================================================================
// KERNEL 2: Pseudo = h@W1 + b1 + 0.1*cnt*y_label; emit Pseudo; yhat = softmax
// =============================================================================
__global__ void pseudo_fused(const float* __restrict__ W1,
                             const float* __restrict__ b1,
                             const float* __restrict__ y_label,
                             float* __restrict__ out_pseudo) {
    int ry = threadIdx.y, c = threadIdx.x;
    int row = blockIdx.x * 4 + ry;
    __shared__ float hr[4][128];
    hr[ry][c]      = g_h[(size_t)row * NHID + c];
    hr[ry][c + 64] = g_h[(size_t)row * NHID + c + 64];
    __syncthreads();
    float acc = b1[c];
#pragma unroll 8
    for (int k = 0; k < NHID; k++) acc += hr[ry][k] * W1[k * NCLS + c];

    // exact label injection (multiplicity-scaled)
    int cnt = g_cnt[row];
    if (cnt) acc += 0.1f * (float)cnt * y_label[(size_t)row * NCLS + c];

    out_pseudo[(size_t)row * NCLS + c] = acc;

    // softmax -> yhat
    __shared__ float sm[4][2];
    int wu = c >> 5, lane = c & 31;
    float m = acc;
#pragma unroll
    for (int o = 16; o; o >>= 1) m = fmaxf(m, __shfl_xor_sync(0xffffffffu, m, o));
    if (lane == 0) sm[ry][wu] = m;
    __syncthreads();
    m = fmaxf(sm[ry][0], sm[ry][1]);
    __syncthreads();
    float e = expf(acc - m);
    float s = e;
#pragma unroll
    for (int o = 16; o; o >>= 1) s += __shfl_xor_sync(0xffffffffu, s, o);
    if (lane == 0) sm[ry][wu] = s;
    __syncthreads();
    s = sm[ry][0] + sm[ry][1];
    g_yhat[(size_t)row * NCLS + c] = e / s;
}

// =============================================================================
// KERNEL 3: edge weights (row-local) + propagation layer 0
// =============================================================================
__global__ void ew_prop0() {
    int row = blockIdx.x;
    __shared__ float yi[NCLS];
    __shared__ int   cs[CAP];
    __shared__ float ws[CAP];
    __shared__ float red[128];
    __shared__ float ssum;
    int t = threadIdx.x;               // 128 threads, 4 warps
    int deg = g_deg[row];
    if (t < NCLS) yi[t] = g_yhat[(size_t)row * NCLS + t];
    if (t < deg)  cs[t] = g_cols[row * CAP + t];
    __syncthreads();

    int w = t >> 5, lane = t & 31;
    for (int n = w; n < deg; n += 4) {
        const float* yj = g_yhat + (size_t)cs[n] * NCLS;
        float p = yi[lane] * yj[lane] + yi[lane + 32] * yj[lane + 32];
#pragma unroll
        for (int o = 16; o; o >>= 1) p += __shfl_down_sync(0xffffffffu, p, o);
        if (lane == 0) ws[n] = p;
    }
    __syncthreads();
    if (t == 0) {
        float s = 0.0f;
        for (int n = 0; n < deg; n++) s += ws[n];
        ssum = fmaxf(s, EPS);
    }
    __syncthreads();
    if (t < deg) {
        float wn = ws[t] / ssum;
        ws[t] = wn;
        g_w[row * CAP + t] = wn;       // reused by layer 1
    }
    __syncthreads();

    // SpMM + residual + L2 normalize
    float s = 0.0f;
    for (int n = 0; n < deg; n++) s += ws[n] * g_h[(size_t)cs[n] * NHID + t];
    float v = 0.9f * s + 0.1f * g_h[(size_t)row * NHID + t];
    red[t] = v * v;
    __syncthreads();
#pragma unroll
    for (int st = 64; st; st >>= 1) {
        if (t < st) red[t] += red[t + st];
        __syncthreads();
    }
    float nrm = fmaxf(sqrtf(red[0]), EPS);
    g_li0[(size_t)row * NHID + t] = v / nrm;
}

// =============================================================================
// KERNEL 4: propagation layer 1 + out = log_softmax(li1 @ W2 + b2)
// =============================================================================
__global__ void prop1_final(const float* __restrict__ W2,
                            const float* __restrict__ b2,
                            float* __restrict__ out) {
    int row = blockIdx.x;
    __shared__ int   cs[CAP];
    __shared__ float ws[CAP];
    __shared__ float red[128];
    __shared__ float li[128];
    __shared__ float pacc[128];
    __shared__ float sm[4];
    int t = threadIdx.x;               // 128 threads
    int deg = g_deg[row];
    if (t < deg) { cs[t] = g_cols[row * CAP + t]; ws[t] = g_w[row * CAP + t]; }
    __syncthreads();

    float s = 0.0f;
    for (int n = 0; n < deg; n++) s += ws[n] * g_li0[(size_t)cs[n] * NHID + t];
    float v = 0.9f * s + 0.1f * g_h[(size_t)row * NHID + t];
    red[t] = v * v;
    __syncthreads();
#pragma unroll
    for (int st = 64; st; st >>= 1) {
        if (t < st) red[t] += red[t + st];
        __syncthreads();
    }
    float nrm = fmaxf(sqrtf(red[0]), EPS);
    li[t] = v / nrm;
    __syncthreads();

    // split-K gemm: out[c] = Σ_k li[k] * W2[k*64+c]
    int c = t & 63, ph = t >> 6;
    float a = 0.0f;
#pragma unroll 8
    for (int k = ph * 64; k < ph * 64 + 64; k++) a += li[k] * W2[k * NCLS + c];
    pacc[t] = a;
    __syncthreads();

    float acc = pacc[c] + pacc[64 + c] + b2[c];   // all threads (t>=64 duplicate)

    // log_softmax over 64 columns (warps 0,1 authoritative)
    int wu = t >> 5, lane = t & 31;
    float m = acc;
#pragma unroll
    for (int o = 16; o; o >>= 1) m = fmaxf(m, __shfl_xor_sync(0xffffffffu, m, o));
    if (lane == 0) sm[wu] = m;
    __syncthreads();
    m = fmaxf(sm[0], sm[1]);
    __syncthreads();
    float sh = acc - m;
    float e = expf(sh);
    float ss = e;
#pragma unroll
    for (int o = 16; o; o >>= 1) ss += __shfl_xor_sync(0xffffffffu, ss, o);
    if (lane == 0) sm[wu] = ss;
    __syncthreads();
    ss = sm[0] + sm[1];
    if (t < 64) out[(size_t)row * NCLS + c] = sh - logf(ss);
}

// ---------------- launch ------------------------------------------------------
extern "C" void kernel_launch(void* const* d_in, const int* in_sizes, int n_in,
                              void* d_out, int out_size) {
    const float* x      = (const float*)d_in[0];
    const float* adj    = (const float*)d_in[1];
    const float* y_lab  = (const float*)d_in[2];
    const int*   idx_tr = (const int*)  d_in[3];
    const float* W0     = (const float*)d_in[4];
    const float* b0     = (const float*)d_in[5];
    const float* W1     = (const float*)d_in[6];
    const float* b1     = (const float*)d_in[7];
    const float* W2     = (const float*)d_in[8];
    const float* b2     = (const float*)d_in[9];
    float* out = (float*)d_out;

    mega1<<<MEGA_BLOCKS, 128>>>(x, W0, b0, adj, idx_tr);
    pseudo_fused<<<NN / 4, dim3(64, 4)>>>(W1, b1, y_lab, out + (size_t)NN * NCLS);
    ew_prop0<<<NN, 128>>>();
    prop1_final<<<NN, 128>>>(W2, b2, out);
}

// round 4
// speedup vs baseline: 1.6069x; 1.6069x over previous
#include <cuda_runtime.h>
#include <cuda_bf16.h>
#include <math.h>

// Problem constants
#define NN      8000
#define NFEAT   512
#define NHID    128
#define NCLS    64
#define CAP     96        // max neighbors per row (E[deg]=16; huge margin)
#define EPS     1e-12f

#define AST 20            // As smem stride (16 + 4 pad)
#define BST 136           // Bs smem stride (128 + 8 pad)

// ---------------- scratch (device globals; no allocation allowed) ------------
__device__ float g_h     [NN * NHID];   // h = relu(x@W0+b0) == h0
__device__ float g_li0   [NN * NHID];
__device__ float g_yhat  [NN * NCLS];
__device__ int   g_cols  [NN * CAP];
__device__ float g_w     [NN * CAP];
__device__ int   g_deg   [NN];
__device__ int   g_cnt   [NN];          // multiplicity of row in idx_train

// ---------------- helpers ----------------------------------------------------
__device__ __forceinline__ unsigned f2tf(float f) {
    unsigned u;
    asm("cvt.rna.tf32.f32 %0, %1;" : "=r"(u) : "f"(f));
    return u;
}

#define MMA_TF32(cc, a, b0_, b1_)                                              \
    asm volatile(                                                              \
        "mma.sync.aligned.m16n8k8.row.col.f32.tf32.tf32.f32 "                  \
        "{%0,%1,%2,%3}, {%4,%5,%6,%7}, {%8,%9}, {%0,%1,%2,%3};"                \
        : "+f"(cc[0]), "+f"(cc[1]), "+f"(cc[2]), "+f"(cc[3])                   \
        : "r"(a[0]), "r"(a[1]), "r"(a[2]), "r"(a[3]), "r"(b0_), "r"(b1_))

// =============================================================================
// KERNEL 1: GEMM1 (tensor tf32-split): h = relu(x @ W0 + b0)
// [8000x512]@[512x128], BM=64 BN=128 BK=16, 128 threads, warp tile 32x64
// =============================================================================
__global__ __launch_bounds__(128) void gemm1_tc(const float* __restrict__ x,
                                                const float* __restrict__ W0,
                                                const float* __restrict__ b0) {
    __shared__ unsigned Ah[64 * AST], Al[64 * AST];
    __shared__ unsigned Bh[16 * BST], Bl[16 * BST];

    const int tid  = threadIdx.x;
    const int warp = tid >> 5;
    const int lane = tid & 31;
    const int m0   = blockIdx.x * 64;
    const int wm   = (warp & 1) * 32;
    const int wn   = (warp >> 1) * 64;

    float c[2][8][4];
#pragma unroll
    for (int mt = 0; mt < 2; mt++)
#pragma unroll
        for (int nt = 0; nt < 8; nt++)
#pragma unroll
            for (int r = 0; r < 4; r++) c[mt][nt][r] = 0.0f;

    const int ra = tid >> 1, ca = (tid & 1) * 8;
    const int rb = tid >> 3, cb = (tid & 7) * 16;
    float4 xa[2], wb[4];

    {
        const float* xp = x + (size_t)(m0 + ra) * NFEAT + ca;
        xa[0] = *(const float4*)(xp);
        xa[1] = *(const float4*)(xp + 4);
        const float* wp = W0 + (size_t)rb * NHID + cb;
#pragma unroll
        for (int i = 0; i < 4; i++) wb[i] = *(const float4*)(wp + i * 4);
    }

    for (int it = 0; it < 32; it++) {
        {
            const float* av = (const float*)xa;
#pragma unroll
            for (int j = 0; j < 8; j++) {
                float v  = av[j];
                unsigned hb = f2tf(v);
                Ah[ra * AST + ca + j] = hb;
                Al[ra * AST + ca + j] = f2tf(v - __uint_as_float(hb));
            }
            const float* bv = (const float*)wb;
#pragma unroll
            for (int j = 0; j < 16; j++) {
                float v  = bv[j];
                unsigned hb = f2tf(v);
                Bh[rb * BST + cb + j] = hb;
                Bl[rb * BST + cb + j] = f2tf(v - __uint_as_float(hb));
            }
        }
        __syncthreads();

        if (it < 31) {
            int k0 = (it + 1) * 16;
            const float* xp = x + (size_t)(m0 + ra) * NFEAT + k0 + ca;
            xa[0] = *(const float4*)(xp);
            xa[1] = *(const float4*)(xp + 4);
            const float* wp = W0 + (size_t)(k0 + rb) * NHID + cb;
#pragma unroll
            for (int i = 0; i < 4; i++) wb[i] = *(const float4*)(wp + i * 4);
        }

#pragma unroll
        for (int ks = 0; ks < 16; ks += 8) {
            unsigned ah[2][4], al[2][4];
            const int arow = wm + (lane >> 2);
            const int ac   = ks + (lane & 3);
#pragma unroll
            for (int mt = 0; mt < 2; mt++) {
                int r = arow + mt * 16;
                ah[mt][0] = Ah[r * AST + ac];
                ah[mt][1] = Ah[(r + 8) * AST + ac];
                ah[mt][2] = Ah[r * AST + ac + 4];
                ah[mt][3] = Ah[(r + 8) * AST + ac + 4];
                al[mt][0] = Al[r * AST + ac];
                al[mt][1] = Al[(r + 8) * AST + ac];
                al[mt][2] = Al[r * AST + ac + 4];
                al[mt][3] = Al[(r + 8) * AST + ac + 4];
            }
#pragma unroll
            for (int nt = 0; nt < 8; nt++) {
                const int bn = wn + nt * 8 + (lane >> 2);
                const int bk = ks + (lane & 3);
                unsigned bh0 = Bh[bk * BST + bn];
                unsigned bh1 = Bh[(bk + 4) * BST + bn];
                unsigned bl0 = Bl[bk * BST + bn];
                unsigned bl1 = Bl[(bk + 4) * BST + bn];
#pragma unroll
                for (int mt = 0; mt < 2; mt++) {
                    MMA_TF32(c[mt][nt], ah[mt], bh0, bh1);
                    MMA_TF32(c[mt][nt], ah[mt], bl0, bl1);
                    MMA_TF32(c[mt][nt], al[mt], bh0, bh1);
                }
            }
        }
        __syncthreads();
    }

#pragma unroll
    for (int nt = 0; nt < 8; nt++) {
        int col = wn + nt * 8 + 2 * (lane & 3);
        float bias0 = b0[col], bias1 = b0[col + 1];
#pragma unroll
        for (int mt = 0; mt < 2; mt++) {
            int r = m0 + wm + mt * 16 + (lane >> 2);
            g_h[(size_t)r * NHID + col]           = fmaxf(c[mt][nt][0] + bias0, 0.0f);
            g_h[(size_t)r * NHID + col + 1]       = fmaxf(c[mt][nt][1] + bias1, 0.0f);
            g_h[(size_t)(r + 8) * NHID + col]     = fmaxf(c[mt][nt][2] + bias0, 0.0f);
            g_h[(size_t)(r + 8) * NHID + col + 1] = fmaxf(c[mt][nt][3] + bias1, 0.0f);
        }
    }
}

// =============================================================================
// KERNEL 2: adjacency extraction (1 warp/row, float4 + shfl-scan) + train cnt
// Light footprint: no smem, low regs -> high occupancy for the DRAM stream.
// =============================================================================
__global__ __launch_bounds__(256) void extract_adj_kernel(const float* __restrict__ adj,
                                                          const int* __restrict__ idx_tr) {
    if (blockIdx.x >= 1000) {
        // train-index multiplicity histogram (1 block)
        int t = threadIdx.x;
        for (int i = t; i < NN; i += 256) g_cnt[i] = 0;
        __syncthreads();
        if (t < 250) {
            atomicAdd(&g_cnt[idx_tr[t]], 1);
            atomicAdd(&g_cnt[idx_tr[t + 250]], 1);
        }
        return;
    }
    int row_id = blockIdx.x * 8 + (threadIdx.x >> 5);
    int lane = threadIdx.x & 31;
    const float* row = adj + (size_t)row_id * NN;
    int base = 0;
    // 8000 = 62*128 + 64
    for (int c0 = 0; c0 < 7936; c0 += 128) {
        float4 v = *(const float4*)(row + c0 + lane * 4);
        unsigned m4 = (v.x != 0.0f) | ((v.y != 0.0f) << 1) |
                      ((v.z != 0.0f) << 2) | ((v.w != 0.0f) << 3);
        int nz = __popc(m4);
        int sc = nz;
#pragma unroll
        for (int o = 1; o < 32; o <<= 1) {
            int t = __shfl_up_sync(0xffffffffu, sc, o);
            if (lane >= o) sc += t;
        }
        int total = __shfl_sync(0xffffffffu, sc, 31);
        if (m4) {
            int p = base + sc - nz;
            int col = c0 + lane * 4;
            if (m4 & 1) { if (p < CAP) g_cols[row_id * CAP + p] = col;     p++; }
            if (m4 & 2) { if (p < CAP) g_cols[row_id * CAP + p] = col + 1; p++; }
            if (m4 & 4) { if (p < CAP) g_cols[row_id * CAP + p] = col + 2; p++; }
            if (m4 & 8) { if (p < CAP) g_cols[row_id * CAP + p] = col + 3; }
        }
        base += total;
    }
    {
        float2 v = *(const float2*)(row + 7936 + lane * 2);
        unsigned m2 = (v.x != 0.0f) | ((v.y != 0.0f) << 1);
        int nz = __popc(m2);
        int sc = nz;
#pragma unroll
        for (int o = 1; o < 32; o <<= 1) {
            int t = __shfl_up_sync(0xffffffffu, sc, o);
            if (lane >= o) sc += t;
        }
        int total = __shfl_sync(0xffffffffu, sc, 31);
        if (m2) {
            int p = base + sc - nz;
            int col = 7936 + lane * 2;
            if (m2 & 1) { if (p < CAP) g_cols[row_id * CAP + p] = col;     p++; }
            if (m2 & 2) { if (p < CAP) g_cols[row_id * CAP + p] = col + 1; }
        }
        base += total;
    }
    if (lane == 0) g_deg[row_id] = base < CAP ? base : CAP;
}

// =============================================================================
// KERNEL 3: Pseudo = h@W1 + b1 + 0.1*cnt*y_label; emit Pseudo; yhat = softmax
// =============================================================================
__global__ void pseudo_fused(const float* __restrict__ W1,
                             const float* __restrict__ b1,
                             const float* __restrict__ y_label,
                             float* __restrict__ out_pseudo) {
    int ry = threadIdx.y, c = threadIdx.x;
    int row = blockIdx.x * 4 + ry;
    __shared__ float hr[4][128];
    hr[ry][c]      = g_h[(size_t)row * NHID + c];
    hr[ry][c + 64] = g_h[(size_t)row * NHID + c + 64];
    __syncthreads();
    float acc = b1[c];
#pragma unroll 8
    for (int k = 0; k < NHID; k++) acc += hr[ry][k] * W1[k * NCLS + c];

    int cnt = g_cnt[row];
    if (cnt) acc += 0.1f * (float)cnt * y_label[(size_t)row * NCLS + c];

    out_pseudo[(size_t)row * NCLS + c] = acc;

    __shared__ float sm[4][2];
    int wu = c >> 5, lane = c & 31;
    float m = acc;
#pragma unroll
    for (int o = 16; o; o >>= 1) m = fmaxf(m, __shfl_xor_sync(0xffffffffu, m, o));
    if (lane == 0) sm[ry][wu] = m;
    __syncthreads();
    m = fmaxf(sm[ry][0], sm[ry][1]);
    __syncthreads();
    float e = expf(acc - m);
    float s = e;
#pragma unroll
    for (int o = 16; o; o >>= 1) s += __shfl_xor_sync(0xffffffffu, s, o);
    if (lane == 0) sm[ry][wu] = s;
    __syncthreads();
    s = sm[ry][0] + sm[ry][1];
    g_yhat[(size_t)row * NCLS + c] = e / s;
}

// =============================================================================
// KERNEL 4: edge weights (row-local) + propagation layer 0
// =============================================================================
__global__ void ew_prop0() {
    int row = blockIdx.x;
    __shared__ float yi[NCLS];
    __shared__ int   cs[CAP];
    __shared__ float ws[CAP];
    __shared__ float red[128];
    __shared__ float ssum;
    int t = threadIdx.x;               // 128 threads, 4 warps
    int deg = g_deg[row];
    if (t < NCLS) yi[t] = g_yhat[(size_t)row * NCLS + t];
    if (t < deg)  cs[t] = g_cols[row * CAP + t];
    __syncthreads();

    int w = t >> 5, lane = t & 31;
    for (int n = w; n < deg; n += 4) {
        const float* yj = g_yhat + (size_t)cs[n] * NCLS;
        float p = yi[lane] * yj[lane] + yi[lane + 32] * yj[lane + 32];
#pragma unroll
        for (int o = 16; o; o >>= 1) p += __shfl_down_sync(0xffffffffu, p, o);
        if (lane == 0) ws[n] = p;
    }
    __syncthreads();
    if (t == 0) {
        float s = 0.0f;
        for (int n = 0; n < deg; n++) s += ws[n];
        ssum = fmaxf(s, EPS);
    }
    __syncthreads();
    if (t < deg) {
        float wn = ws[t] / ssum;
        ws[t] = wn;
        g_w[row * CAP + t] = wn;       // reused by layer 1
    }
    __syncthreads();

    float s = 0.0f;
    for (int n = 0; n < deg; n++) s += ws[n] * g_h[(size_t)cs[n] * NHID + t];
    float v = 0.9f * s + 0.1f * g_h[(size_t)row * NHID + t];
    red[t] = v * v;
    __syncthreads();
#pragma unroll
    for (int st = 64; st; st >>= 1) {
        if (t < st) red[t] += red[t + st];
        __syncthreads();
    }
    float nrm = fmaxf(sqrtf(red[0]), EPS);
    g_li0[(size_t)row * NHID + t] = v / nrm;
}

// =============================================================================
// KERNEL 5: propagation layer 1 + out = log_softmax(li1 @ W2 + b2)
// =============================================================================
__global__ void prop1_final(const float* __restrict__ W2,
                            const float* __restrict__ b2,
                            float* __restrict__ out) {
    int row = blockIdx.x;
    __shared__ int   cs[CAP];
    __shared__ float ws[CAP];
    __shared__ float red[128];
    __shared__ float li[128];
    __shared__ float pacc[128];
    __shared__ float sm[4];
    int t = threadIdx.x;               // 128 threads
    int deg = g_deg[row];
    if (t < deg) { cs[t] = g_cols[row * CAP + t]; ws[t] = g_w[row * CAP + t]; }
    __syncthreads();

    float s = 0.0f;
    for (int n = 0; n < deg; n++) s += ws[n] * g_li0[(size_t)cs[n] * NHID + t];
    float v = 0.9f * s + 0.1f * g_h[(size_t)row * NHID + t];
    red[t] = v * v;
    __syncthreads();
#pragma unroll
    for (int st = 64; st; st >>= 1) {
        if (t < st) red[t] += red[t + st];
        __syncthreads();
    }
    float nrm = fmaxf(sqrtf(red[0]), EPS);
    li[t] = v / nrm;
    __syncthreads();

    // split-K gemm: out[c] = Σ_k li[k] * W2[k*64+c]
    int c = t & 63, ph = t >> 6;
    float a = 0.0f;
#pragma unroll 8
    for (int k = ph * 64; k < ph * 64 + 64; k++) a += li[k] * W2[k * NCLS + c];
    pacc[t] = a;
    __syncthreads();

    float acc = pacc[c] + pacc[64 + c] + b2[c];

    int wu = t >> 5, lane = t & 31;
    float m = acc;
#pragma unroll
    for (int o = 16; o; o >>= 1) m = fmaxf(m, __shfl_xor_sync(0xffffffffu, m, o));
    if (lane == 0) sm[wu] = m;
    __syncthreads();
    m = fmaxf(sm[0], sm[1]);
    __syncthreads();
    float sh = acc - m;
    float e = expf(sh);
    float ss = e;
#pragma unroll
    for (int o = 16; o; o >>= 1) ss += __shfl_xor_sync(0xffffffffu, ss, o);
    if (lane == 0) sm[wu] = ss;
    __syncthreads();
    ss = sm[0] + sm[1];
    if (t < 64) out[(size_t)row * NCLS + c] = sh - logf(ss);
}

// ---------------- launch ------------------------------------------------------
extern "C" void kernel_launch(void* const* d_in, const int* in_sizes, int n_in,
                              void* d_out, int out_size) {
    const float* x      = (const float*)d_in[0];
    const float* adj    = (const float*)d_in[1];
    const float* y_lab  = (const float*)d_in[2];
    const int*   idx_tr = (const int*)  d_in[3];
    const float* W0     = (const float*)d_in[4];
    const float* b0     = (const float*)d_in[5];
    const float* W1     = (const float*)d_in[6];
    const float* b1     = (const float*)d_in[7];
    const float* W2     = (const float*)d_in[8];
    const float* b2     = (const float*)d_in[9];
    float* out = (float*)d_out;

    gemm1_tc<<<NN / 64, 128>>>(x, W0, b0);
    extract_adj_kernel<<<1001, 256>>>(adj, idx_tr);
    pseudo_fused<<<NN / 4, dim3(64, 4)>>>(W1, b1, y_lab, out + (size_t)NN * NCLS);
    ew_prop0<<<NN, 128>>>();
    prop1_final<<<NN, 128>>>(W2, b2, out);
}

// round 5
// speedup vs baseline: 2.0509x; 1.2763x over previous
#include <cuda_runtime.h>
#include <cuda_bf16.h>
#include <math.h>

// Problem constants
#define NN      8000
#define NFEAT   512
#define NHID    128
#define NCLS    64
#define CAP     96        // max neighbors per row (E[deg]=16; huge margin)
#define EPS     1e-12f

#define AST 20            // As smem stride (16 + 4 pad)
#define BST 136           // Bs smem stride (128 + 8 pad)

// ---------------- scratch (device globals; no allocation allowed) ------------
__device__ float g_h     [NN * NHID];   // h = relu(x@W0+b0) == h0
__device__ float g_li0   [NN * NHID];
__device__ float g_yhat  [NN * NCLS];
__device__ int   g_cols  [NN * CAP];
__device__ float g_w     [NN * CAP];
__device__ int   g_deg   [NN];
__device__ int   g_cnt   [NN];          // multiplicity of row in idx_train

// ---------------- helpers ----------------------------------------------------
__device__ __forceinline__ unsigned f2tf(float f) {
    unsigned u;
    asm("cvt.rna.tf32.f32 %0, %1;" : "=r"(u) : "f"(f));
    return u;
}

#define MMA_TF32(cc, a, b0_, b1_)                                              \
    asm volatile(                                                              \
        "mma.sync.aligned.m16n8k8.row.col.f32.tf32.tf32.f32 "                  \
        "{%0,%1,%2,%3}, {%4,%5,%6,%7}, {%8,%9}, {%0,%1,%2,%3};"                \
        : "+f"(cc[0]), "+f"(cc[1]), "+f"(cc[2]), "+f"(cc[3])                   \
        : "r"(a[0]), "r"(a[1]), "r"(a[2]), "r"(a[3]), "r"(b0_), "r"(b1_))

// =============================================================================
// KERNEL 1: GEMM1 (tensor tf32-split): h = relu(x @ W0 + b0)
// =============================================================================
__global__ __launch_bounds__(128) void gemm1_tc(const float* __restrict__ x,
                                                const float* __restrict__ W0,
                                                const float* __restrict__ b0) {
    __shared__ unsigned Ah[64 * AST], Al[64 * AST];
    __shared__ unsigned Bh[16 * BST], Bl[16 * BST];

    const int tid  = threadIdx.x;
    const int warp = tid >> 5;
    const int lane = tid & 31;
    const int m0   = blockIdx.x * 64;
    const int wm   = (warp & 1) * 32;
    const int wn   = (warp >> 1) * 64;

    float c[2][8][4];
#pragma unroll
    for (int mt = 0; mt < 2; mt++)
#pragma unroll
        for (int nt = 0; nt < 8; nt++)
#pragma unroll
            for (int r = 0; r < 4; r++) c[mt][nt][r] = 0.0f;

    const int ra = tid >> 1, ca = (tid & 1) * 8;
    const int rb = tid >> 3, cb = (tid & 7) * 16;
    float4 xa[2], wb[4];

    {
        const float* xp = x + (size_t)(m0 + ra) * NFEAT + ca;
        xa[0] = *(const float4*)(xp);
        xa[1] = *(const float4*)(xp + 4);
        const float* wp = W0 + (size_t)rb * NHID + cb;
#pragma unroll
        for (int i = 0; i < 4; i++) wb[i] = *(const float4*)(wp + i * 4);
    }

    for (int it = 0; it < 32; it++) {
        {
            const float* av = (const float*)xa;
#pragma unroll
            for (int j = 0; j < 8; j++) {
                float v  = av[j];
                unsigned hb = f2tf(v);
                Ah[ra * AST + ca + j] = hb;
                Al[ra * AST + ca + j] = f2tf(v - __uint_as_float(hb));
            }
            const float* bv = (const float*)wb;
#pragma unroll
            for (int j = 0; j < 16; j++) {
                float v  = bv[j];
                unsigned hb = f2tf(v);
                Bh[rb * BST + cb + j] = hb;
                Bl[rb * BST + cb + j] = f2tf(v - __uint_as_float(hb));
            }
        }
        __syncthreads();

        if (it < 31) {
            int k0 = (it + 1) * 16;
            const float* xp = x + (size_t)(m0 + ra) * NFEAT + k0 + ca;
            xa[0] = *(const float4*)(xp);
            xa[1] = *(const float4*)(xp + 4);
            const float* wp = W0 + (size_t)(k0 + rb) * NHID + cb;
#pragma unroll
            for (int i = 0; i < 4; i++) wb[i] = *(const float4*)(wp + i * 4);
        }

#pragma unroll
        for (int ks = 0; ks < 16; ks += 8) {
            unsigned ah[2][4], al[2][4];
            const int arow = wm + (lane >> 2);
            const int ac   = ks + (lane & 3);
#pragma unroll
            for (int mt = 0; mt < 2; mt++) {
                int r = arow + mt * 16;
                ah[mt][0] = Ah[r * AST + ac];
                ah[mt][1] = Ah[(r + 8) * AST + ac];
                ah[mt][2] = Ah[r * AST + ac + 4];
                ah[mt][3] = Ah[(r + 8) * AST + ac + 4];
                al[mt][0] = Al[r * AST + ac];
                al[mt][1] = Al[(r + 8) * AST + ac];
                al[mt][2] = Al[r * AST + ac + 4];
                al[mt][3] = Al[(r + 8) * AST + ac + 4];
            }
#pragma unroll
            for (int nt = 0; nt < 8; nt++) {
                const int bn = wn + nt * 8 + (lane >> 2);
                const int bk = ks + (lane & 3);
                unsigned bh0 = Bh[bk * BST + bn];
                unsigned bh1 = Bh[(bk + 4) * BST + bn];
                unsigned bl0 = Bl[bk * BST + bn];
                unsigned bl1 = Bl[(bk + 4) * BST + bn];
#pragma unroll
                for (int mt = 0; mt < 2; mt++) {
                    MMA_TF32(c[mt][nt], ah[mt], bh0, bh1);
                    MMA_TF32(c[mt][nt], ah[mt], bl0, bl1);
                    MMA_TF32(c[mt][nt], al[mt], bh0, bh1);
                }
            }
        }
        __syncthreads();
    }

#pragma unroll
    for (int nt = 0; nt < 8; nt++) {
        int col = wn + nt * 8 + 2 * (lane & 3);
        float bias0 = b0[col], bias1 = b0[col + 1];
#pragma unroll
        for (int mt = 0; mt < 2; mt++) {
            int r = m0 + wm + mt * 16 + (lane >> 2);
            g_h[(size_t)r * NHID + col]           = fmaxf(c[mt][nt][0] + bias0, 0.0f);
            g_h[(size_t)r * NHID + col + 1]       = fmaxf(c[mt][nt][1] + bias1, 0.0f);
            g_h[(size_t)(r + 8) * NHID + col]     = fmaxf(c[mt][nt][2] + bias0, 0.0f);
            g_h[(size_t)(r + 8) * NHID + col + 1] = fmaxf(c[mt][nt][3] + bias1, 0.0f);
        }
    }
}

// =============================================================================
// KERNEL cnt: train-index multiplicity histogram (tiny)
// =============================================================================
__global__ void cnt_kernel(const int* __restrict__ idx_tr) {
    int t = threadIdx.x;
    for (int i = t; i < NN; i += 256) g_cnt[i] = 0;
    __syncthreads();
    if (t < 250) {
        atomicAdd(&g_cnt[idx_tr[t]], 1);
        atomicAdd(&g_cnt[idx_tr[t + 250]], 1);
    }
}

// =============================================================================
// KERNEL 2: adjacency extraction (1 warp/row), ballot fast-path for empty chunks
// =============================================================================
__global__ __launch_bounds__(256) void extract_adj_kernel(const float* __restrict__ adj) {
    int row_id = blockIdx.x * 8 + (threadIdx.x >> 5);
    int lane = threadIdx.x & 31;
    const float* row = adj + (size_t)row_id * NN;
    int base = 0;
    // 8000 = 62*128 + 64
    for (int c0 = 0; c0 < 7936; c0 += 128) {
        float4 v = *(const float4*)(row + c0 + lane * 4);
        unsigned m4 = (v.x != 0.0f) | ((v.y != 0.0f) << 1) |
                      ((v.z != 0.0f) << 2) | ((v.w != 0.0f) << 3);
        unsigned act = __ballot_sync(0xffffffffu, m4 != 0);
        if (act == 0) continue;                 // common case (~77%)
        int nz = __popc(m4);
        // serial over active lanes, column order preserved
        while (act) {
            int l   = __ffs(act) - 1;
            int c_l = __shfl_sync(0xffffffffu, nz, l);
            if (lane == l) {
                int p = base;
                int col = c0 + lane * 4;
                if (m4 & 1) { if (p < CAP) g_cols[row_id * CAP + p] = col;     p++; }
                if (m4 & 2) { if (p < CAP) g_cols[row_id * CAP + p] = col + 1; p++; }
                if (m4 & 4) { if (p < CAP) g_cols[row_id * CAP + p] = col + 2; p++; }
                if (m4 & 8) { if (p < CAP) g_cols[row_id * CAP + p] = col + 3; }
            }
            base += c_l;
            act &= act - 1;
        }
    }
    // tail: 64 columns
    {
        float2 v = *(const float2*)(row + 7936 + lane * 2);
        unsigned m2 = (v.x != 0.0f) | ((v.y != 0.0f) << 1);
        unsigned act = __ballot_sync(0xffffffffu, m2 != 0);
        int nz = __popc(m2);
        while (act) {
            int l   = __ffs(act) - 1;
            int c_l = __shfl_sync(0xffffffffu, nz, l);
            if (lane == l) {
                int p = base;
                int col = 7936 + lane * 2;
                if (m2 & 1) { if (p < CAP) g_cols[row_id * CAP + p] = col;     p++; }
                if (m2 & 2) { if (p < CAP) g_cols[row_id * CAP + p] = col + 1; }
            }
            base += c_l;
            act &= act - 1;
        }
    }
    if (lane == 0) g_deg[row_id] = base < CAP ? base : CAP;
}

// =============================================================================
// KERNEL 3: Pseudo = h@W1 + b1 + 0.1*cnt*y_label; emit Pseudo; yhat = softmax
// =============================================================================
__global__ void pseudo_fused(const float* __restrict__ W1,
                             const float* __restrict__ b1,
                             const float* __restrict__ y_label,
                             float* __restrict__ out_pseudo) {
    int ry = threadIdx.y, c = threadIdx.x;
    int row = blockIdx.x * 4 + ry;
    __shared__ float hr[4][128];
    hr[ry][c]      = g_h[(size_t)row * NHID + c];
    hr[ry][c + 64] = g_h[(size_t)row * NHID + c + 64];
    __syncthreads();
    float acc = b1[c];
#pragma unroll 8
    for (int k = 0; k < NHID; k++) acc += hr[ry][k] * W1[k * NCLS + c];

    int cnt = g_cnt[row];
    if (cnt) acc += 0.1f * (float)cnt * y_label[(size_t)row * NCLS + c];

    out_pseudo[(size_t)row * NCLS + c] = acc;

    __shared__ float sm[4][2];
    int wu = c >> 5, lane = c & 31;
    float m = acc;
#pragma unroll
    for (int o = 16; o; o >>= 1) m = fmaxf(m, __shfl_xor_sync(0xffffffffu, m, o));
    if (lane == 0) sm[ry][wu] = m;
    __syncthreads();
    m = fmaxf(sm[ry][0], sm[ry][1]);
    __syncthreads();
    float e = expf(acc - m);
    float s = e;
#pragma unroll
    for (int o = 16; o; o >>= 1) s += __shfl_xor_sync(0xffffffffu, s, o);
    if (lane == 0) sm[ry][wu] = s;
    __syncthreads();
    s = sm[ry][0] + sm[ry][1];
    g_yhat[(size_t)row * NCLS + c] = e / s;
}

// =============================================================================
// KERNEL 4: edge weights (row-local) + propagation layer 0
// =============================================================================
__global__ void ew_prop0() {
    int row = blockIdx.x;
    __shared__ float yi[NCLS];
    __shared__ int   cs[CAP];
    __shared__ float ws[CAP];
    __shared__ float red[128];
    __shared__ float ssum;
    int t = threadIdx.x;               // 128 threads, 4 warps
    int deg = g_deg[row];
    if (t < NCLS) yi[t] = g_yhat[(size_t)row * NCLS + t];
    if (t < deg)  cs[t] = g_cols[row * CAP + t];
    __syncthreads();

    int w = t >> 5, lane = t & 31;
    for (int n = w; n < deg; n += 4) {
        const float* yj = g_yhat + (size_t)cs[n] * NCLS;
        float p = yi[lane] * yj[lane] + yi[lane + 32] * yj[lane + 32];
#pragma unroll
        for (int o = 16; o; o >>= 1) p += __shfl_down_sync(0xffffffffu, p, o);
        if (lane == 0) ws[n] = p;
    }
    __syncthreads();
    if (t == 0) {
        float s = 0.0f;
        for (int n = 0; n < deg; n++) s += ws[n];
        ssum = fmaxf(s, EPS);
    }
    __syncthreads();
    if (t < deg) {
        float wn = ws[t] / ssum;
        ws[t] = wn;
        g_w[row * CAP + t] = wn;       // reused by layer 1
    }
    __syncthreads();

    float s = 0.0f;
    for (int n = 0; n < deg; n++) s += ws[n] * g_h[(size_t)cs[n] * NHID + t];
    float v = 0.9f * s + 0.1f * g_h[(size_t)row * NHID + t];
    red[t] = v * v;
    __syncthreads();
#pragma unroll
    for (int st = 64; st; st >>= 1) {
        if (t < st) red[t] += red[t + st];
        __syncthreads();
    }
    float nrm = fmaxf(sqrtf(red[0]), EPS);
    g_li0[(size_t)row * NHID + t] = v / nrm;
}

// =============================================================================
// KERNEL 5: propagation layer 1 + out = log_softmax(li1 @ W2 + b2)
// =============================================================================
__global__ void prop1_final(const float* __restrict__ W2,
                            const float* __restrict__ b2,
                            float* __restrict__ out) {
    int row = blockIdx.x;
    __shared__ int   cs[CAP];
    __shared__ float ws[CAP];
    __shared__ float red[128];
    __shared__ float li[128];
    __shared__ float pacc[128];
    __shared__ float sm[4];
    int t = threadIdx.x;               // 128 threads
    int deg = g_deg[row];
    if (t < deg) { cs[t] = g_cols[row * CAP + t]; ws[t] = g_w[row * CAP + t]; }
    __syncthreads();

    float s = 0.0f;
    for (int n = 0; n < deg; n++) s += ws[n] * g_li0[(size_t)cs[n] * NHID + t];
    float v = 0.9f * s + 0.1f * g_h[(size_t)row * NHID + t];
    red[t] = v * v;
    __syncthreads();
#pragma unroll
    for (int st = 64; st; st >>= 1) {
        if (t < st) red[t] += red[t + st];
        __syncthreads();
    }
    float nrm = fmaxf(sqrtf(red[0]), EPS);
    li[t] = v / nrm;
    __syncthreads();

    int c = t & 63, ph = t >> 6;
    float a = 0.0f;
#pragma unroll 8
    for (int k = ph * 64; k < ph * 64 + 64; k++) a += li[k] * W2[k * NCLS + c];
    pacc[t] = a;
    __syncthreads();

    float acc = pacc[c] + pacc[64 + c] + b2[c];

    int wu = t >> 5, lane = t & 31;
    float m = acc;
#pragma unroll
    for (int o = 16; o; o >>= 1) m = fmaxf(m, __shfl_xor_sync(0xffffffffu, m, o));
    if (lane == 0) sm[wu] = m;
    __syncthreads();
    m = fmaxf(sm[0], sm[1]);
    __syncthreads();
    float sh = acc - m;
    float e = expf(sh);
    float ss = e;
#pragma unroll
    for (int o = 16; o; o >>= 1) ss += __shfl_xor_sync(0xffffffffu, ss, o);
    if (lane == 0) sm[wu] = ss;
    __syncthreads();
    ss = sm[0] + sm[1];
    if (t < 64) out[(size_t)row * NCLS + c] = sh - logf(ss);
}

// ---------------- launch: 2-stream fork/join inside the captured graph --------
extern "C" void kernel_launch(void* const* d_in, const int* in_sizes, int n_in,
                              void* d_out, int out_size) {
    const float* x      = (const float*)d_in[0];
    const float* adj    = (const float*)d_in[1];
    const float* y_lab  = (const float*)d_in[2];
    const int*   idx_tr = (const int*)  d_in[3];
    const float* W0     = (const float*)d_in[4];
    const float* b0     = (const float*)d_in[5];
    const float* W1     = (const float*)d_in[6];
    const float* b1     = (const float*)d_in[7];
    const float* W2     = (const float*)d_in[8];
    const float* b2     = (const float*)d_in[9];
    float* out = (float*)d_out;

    static cudaStream_t s2 = nullptr;
    static cudaEvent_t evFork = nullptr, evCnt = nullptr, evExt = nullptr;
    if (s2 == nullptr) {                       // first (non-captured) call only
        cudaStreamCreateWithFlags(&s2, cudaStreamNonBlocking);
        cudaEventCreateWithFlags(&evFork, cudaEventDisableTiming);
        cudaEventCreateWithFlags(&evCnt,  cudaEventDisableTiming);
        cudaEventCreateWithFlags(&evExt,  cudaEventDisableTiming);
    }

    // fork: stream2 runs the DRAM-bound chain concurrently with the GEMM chain
    cudaEventRecord(evFork, 0);
    cudaStreamWaitEvent(s2, evFork, 0);

    cnt_kernel<<<1, 256, 0, s2>>>(idx_tr);
    cudaEventRecord(evCnt, s2);
    extract_adj_kernel<<<1000, 256, 0, s2>>>(adj);
    cudaEventRecord(evExt, s2);

    gemm1_tc<<<NN / 64, 128>>>(x, W0, b0);                       // stream 0
    cudaStreamWaitEvent(0, evCnt, 0);                            // need g_cnt
    pseudo_fused<<<NN / 4, dim3(64, 4)>>>(W1, b1, y_lab, out + (size_t)NN * NCLS);
    cudaStreamWaitEvent(0, evExt, 0);                            // need cols/deg
    ew_prop0<<<NN, 128>>>();
    prop1_final<<<NN, 128>>>(W2, b2, out);
}